// round 12
// baseline (speedup 1.0000x reference)
#include <cuda_runtime.h>
#include <math.h>

#define DIM 1024
#define WARPS_PER_BLOCK 4
#define NTHREADS 128
#define GRID_BLOCKS 608          // 4 blocks * 152 SMs
#define F4_PER_ROW 256
#define NSTAGE 3                 // 2 rows in flight per warp

__device__ __forceinline__ void cp_async16(void* smem_dst, const void* gsrc) {
    unsigned saddr = (unsigned)__cvta_generic_to_shared(smem_dst);
    asm volatile("cp.async.cg.shared.global [%0], [%1], 16;\n" :: "r"(saddr), "l"(gsrc));
}
__device__ __forceinline__ void cp_commit() { asm volatile("cp.async.commit_group;\n"); }
template<int N> __device__ __forceinline__ void cp_wait() {
    asm volatile("cp.async.wait_group %0;\n" :: "n"(N));
}

__global__ __launch_bounds__(NTHREADS)
void iln_kernel(const float* __restrict__ x,
                const float* __restrict__ weight,
                const float* __restrict__ bias,
                float* __restrict__ out,
                int n_rows)
{
    __shared__ int   s_w[DIM];
    __shared__ float s_fb[DIM];          // bias_int / 256 as float (exact)
    __shared__ int   s_lut[32];
    __shared__ float4 s_x[WARPS_PER_BLOCK][NSTAGE][F4_PER_ROW];

    const int tid = threadIdx.x;

    // 32-entry isqrt LUT, exact: round((1<<15)/sqrt(2^parity*(1+m/16)))
    if (tid < 32) {
        const int parity = tid >> 4;
        const int mant = tid & 15;
        const double val = (double)(1 << parity) * (1.0 + (double)mant * 0.0625);
        s_lut[tid] = (int)llrint(32768.0 / sqrt(val));
    }
    // Quantize weight/bias (round-half-even matches jnp.round).
    for (int i = tid; i < DIM; i += NTHREADS) {
        s_w[i]  = __float2int_rn(weight[i] * 256.0f);
        s_fb[i] = (float)__float2int_rn(bias[i] * 256.0f) * 0.00390625f;
    }
    __syncthreads();

    const int warp = tid >> 5;
    const int lane = tid & 31;
    const int stride = GRID_BLOCKS * WARPS_PER_BLOCK;
    int row = blockIdx.x * WARPS_PER_BLOCK + warp;

    // Prologue: prefetch up to 2 rows ahead (one commit group each)
    #pragma unroll
    for (int p = 0; p < NSTAGE - 1; p++) {
        const int r = row + p * stride;
        if (r < n_rows) {
            const float4* __restrict__ xr = (const float4*)(x + (size_t)r * DIM);
            #pragma unroll
            for (int j = 0; j < 8; j++)
                cp_async16(&s_x[warp][p][j * 32 + lane], &xr[j * 32 + lane]);
            cp_commit();
        }
    }

    int cur = 0;
    for (; row < n_rows; row += stride) {
        const int nxt = row + (NSTAGE - 1) * stride;   // prefetch 2 ahead
        if (nxt < n_rows) {
            const int buf = (cur + NSTAGE - 1) % NSTAGE;
            const float4* __restrict__ xn = (const float4*)(x + (size_t)nxt * DIM);
            #pragma unroll
            for (int j = 0; j < 8; j++)
                cp_async16(&s_x[warp][buf][j * 32 + lane], &xn[j * 32 + lane]);
            cp_commit();
            cp_wait<NSTAGE - 1>();   // current row's group must be complete
        } else {
            cp_wait<0>();
        }

        // ---- phase 1: smem -> int regs, partial sums ----
        int xi[32];
        int sum = 0, sumsq = 0;      // row sumsq ~1e8 << 2^31, exact
        #pragma unroll
        for (int j = 0; j < 8; j++) {
            const float4 v = s_x[warp][cur][j * 32 + lane];
            const int a0 = __float2int_rn(v.x);
            const int a1 = __float2int_rn(v.y);
            const int a2 = __float2int_rn(v.z);
            const int a3 = __float2int_rn(v.w);
            xi[j * 4 + 0] = a0; xi[j * 4 + 1] = a1;
            xi[j * 4 + 2] = a2; xi[j * 4 + 3] = a3;
            sum   += a0 + a1 + a2 + a3;
            sumsq += a0 * a0 + a1 * a1 + a2 * a2 + a3 * a3;
        }

        sum   = __reduce_add_sync(0xffffffffu, sum);
        sumsq = __reduce_add_sync(0xffffffffu, sumsq);

        const int mean = (sum * 64) >> 16;                 // fixed-point mean
        const long long ssy = (long long)sumsq
                            - 2LL * (long long)mean * (long long)sum
                            + (long long)DIM * (long long)mean * (long long)mean;
        long long var = (ssy * 64) >> 16;
        if (var < 1) var = 1;

        const int k = 63 - __clzll((unsigned long long)var);   // floor(log2), exact
        const int sa = k - 4;
        const int mant = (sa >= 0) ? (int)((var >> sa) & 15)
                                   : (int)((var << (-sa)) & 15);
        const int inv = s_lut[((k & 1) << 4) | mant];
        const int ts = (k >> 1) + 15;      // p + SHIFT(0) + Q_LUT(15), ts in [15, ~24]
        const int minv = mean * inv;       // hoisted: s = a*inv - minv

        float4* __restrict__ orow = (float4*)(out + (size_t)row * DIM);
        #pragma unroll
        for (int j = 0; j < 8; j++) {
            const int c4 = j * 32 + lane;
            const int4   w4 = ((const int4*)s_w)[c4];
            const float4 f4 = ((const float4*)s_fb)[c4];
            float4 o;
            // per element: IMAD, IMAD.WIDE, SHF, I2F, FFMA (exact; fits int32 since
            // |s|<2^25, |w|<2^10 => |prod|<2^34, >>ts>=15 => |res|<2^19)
            {
                const int s = xi[j*4+0] * inv - minv;
                const int lo = s * w4.x, hi = __mulhi(s, w4.x);
                o.x = fmaf((float)(int)__funnelshift_r((unsigned)lo, (unsigned)hi, ts),
                           0.00390625f, f4.x);
            }
            {
                const int s = xi[j*4+1] * inv - minv;
                const int lo = s * w4.y, hi = __mulhi(s, w4.y);
                o.y = fmaf((float)(int)__funnelshift_r((unsigned)lo, (unsigned)hi, ts),
                           0.00390625f, f4.y);
            }
            {
                const int s = xi[j*4+2] * inv - minv;
                const int lo = s * w4.z, hi = __mulhi(s, w4.z);
                o.z = fmaf((float)(int)__funnelshift_r((unsigned)lo, (unsigned)hi, ts),
                           0.00390625f, f4.z);
            }
            {
                const int s = xi[j*4+3] * inv - minv;
                const int lo = s * w4.w, hi = __mulhi(s, w4.w);
                o.w = fmaf((float)(int)__funnelshift_r((unsigned)lo, (unsigned)hi, ts),
                           0.00390625f, f4.w);
            }
            __stcs(&orow[c4], o);
        }

        cur = (cur + 1) % NSTAGE;
    }
}

extern "C" void kernel_launch(void* const* d_in, const int* in_sizes, int n_in,
                              void* d_out, int out_size) {
    const float* x      = (const float*)d_in[0];
    const float* weight = (const float*)d_in[1];
    const float* bias   = (const float*)d_in[2];
    // d_in[3] (isqrt_lut) intentionally unused: LUT recomputed exactly in-kernel.
    float* out = (float*)d_out;

    const int n_rows = in_sizes[0] / DIM;
    iln_kernel<<<GRID_BLOCKS, NTHREADS>>>(x, weight, bias, out, n_rows);
}

// round 13
// speedup vs baseline: 1.6154x; 1.6154x over previous
#include <cuda_runtime.h>
#include <math.h>

#define DIM 1024
#define WARPS_PER_BLOCK 8
#define NTHREADS 256

// Integer LayerNorm, warp per row, DOUBLE-READ design:
// pass1: LDG row -> sums -> REDUX -> stats (row discarded from regs)
// pass2: LDG row again (L1/L2-hot) -> 5-instr/elem epilogue -> STG
// Memory is in flight during both phases; no smem x-buffer => 32 warps/SM.
__global__ __launch_bounds__(NTHREADS, 4)
void iln_kernel(const float* __restrict__ x,
                const float* __restrict__ weight,
                const float* __restrict__ bias,
                float* __restrict__ out,
                int n_rows)
{
    __shared__ int   s_w[DIM];
    __shared__ float s_fb[DIM];          // bias_int / 256 as float (exact)
    __shared__ int   s_lut[32];

    const int tid = threadIdx.x;

    // 32-entry isqrt LUT, exact: round((1<<15)/sqrt(2^parity*(1+m/16)))
    if (tid < 32) {
        const int parity = tid >> 4;
        const int mant = tid & 15;
        const double val = (double)(1 << parity) * (1.0 + (double)mant * 0.0625);
        s_lut[tid] = (int)llrint(32768.0 / sqrt(val));
    }
    // Quantize weight/bias (round-half-even matches jnp.round)
    for (int i = tid; i < DIM; i += NTHREADS) {
        s_w[i]  = __float2int_rn(weight[i] * 256.0f);
        s_fb[i] = (float)__float2int_rn(bias[i] * 256.0f) * 0.00390625f;
    }
    __syncthreads();

    const int warp = tid >> 5;
    const int lane = tid & 31;
    const int row = blockIdx.x * WARPS_PER_BLOCK + warp;
    if (row >= n_rows) return;

    const float4* __restrict__ xr = (const float4*)(x + (size_t)row * DIM);

    // ---- pass 1: front-batched loads, sums only (row not kept) ----
    float4 v[8];
    #pragma unroll
    for (int j = 0; j < 8; j++) v[j] = xr[j * 32 + lane];

    int sum = 0, sumsq = 0;              // row sumsq ~1e8 << 2^31, exact
    #pragma unroll
    for (int j = 0; j < 8; j++) {
        const int a0 = __float2int_rn(v[j].x);
        const int a1 = __float2int_rn(v[j].y);
        const int a2 = __float2int_rn(v[j].z);
        const int a3 = __float2int_rn(v[j].w);
        sum   += a0 + a1 + a2 + a3;
        sumsq += a0 * a0 + a1 * a1 + a2 * a2 + a3 * a3;
    }
    sum   = __reduce_add_sync(0xffffffffu, sum);
    sumsq = __reduce_add_sync(0xffffffffu, sumsq);

    const int mean = (sum * 64) >> 16;                 // fixed-point mean
    const long long ssy = (long long)sumsq
                        - 2LL * (long long)mean * (long long)sum
                        + (long long)DIM * (long long)mean * (long long)mean;
    long long var = (ssy * 64) >> 16;
    if (var < 1) var = 1;

    const int k = 63 - __clzll((unsigned long long)var);   // floor(log2), exact
    const int sa = k - 4;
    const int mant = (sa >= 0) ? (int)((var >> sa) & 15)
                               : (int)((var << (-sa)) & 15);
    const int inv = s_lut[((k & 1) << 4) | mant];
    const int ts = (k >> 1) + 15;        // p + SHIFT(0) + Q_LUT(15), ts in [15, ~24]
    const int minv = mean * inv;         // hoisted: s = a*inv - minv

    // ---- pass 2: re-load row (L1/L2-hot), epilogue, store ----
    #pragma unroll
    for (int j = 0; j < 8; j++) v[j] = xr[j * 32 + lane];

    float4* __restrict__ orow = (float4*)(out + (size_t)row * DIM);
    #pragma unroll
    for (int j = 0; j < 8; j++) {
        const int c4 = j * 32 + lane;
        const int4   w4 = ((const int4*)s_w)[c4];
        const float4 f4 = ((const float4*)s_fb)[c4];
        float4 o;
        // per element: F2I, IMAD, IMAD.WIDE, SHF, I2F, FFMA (exact; result of the
        // >> fits int32 since |s|<2^25, |w|<2^10 => |prod|<2^34, >>ts>=15 => <2^19)
        {
            const int s = __float2int_rn(v[j].x) * inv - minv;
            const int lo = s * w4.x, hi = __mulhi(s, w4.x);
            o.x = fmaf((float)(int)__funnelshift_r((unsigned)lo, (unsigned)hi, ts),
                       0.00390625f, f4.x);
        }
        {
            const int s = __float2int_rn(v[j].y) * inv - minv;
            const int lo = s * w4.y, hi = __mulhi(s, w4.y);
            o.y = fmaf((float)(int)__funnelshift_r((unsigned)lo, (unsigned)hi, ts),
                       0.00390625f, f4.y);
        }
        {
            const int s = __float2int_rn(v[j].z) * inv - minv;
            const int lo = s * w4.z, hi = __mulhi(s, w4.z);
            o.z = fmaf((float)(int)__funnelshift_r((unsigned)lo, (unsigned)hi, ts),
                       0.00390625f, f4.z);
        }
        {
            const int s = __float2int_rn(v[j].w) * inv - minv;
            const int lo = s * w4.w, hi = __mulhi(s, w4.w);
            o.w = fmaf((float)(int)__funnelshift_r((unsigned)lo, (unsigned)hi, ts),
                       0.00390625f, f4.w);
        }
        __stcs(&orow[c4], o);
    }
}

extern "C" void kernel_launch(void* const* d_in, const int* in_sizes, int n_in,
                              void* d_out, int out_size) {
    const float* x      = (const float*)d_in[0];
    const float* weight = (const float*)d_in[1];
    const float* bias   = (const float*)d_in[2];
    // d_in[3] (isqrt_lut) intentionally unused: LUT recomputed exactly in-kernel.
    float* out = (float*)d_out;

    const int n_rows = in_sizes[0] / DIM;
    const int blocks = (n_rows + WARPS_PER_BLOCK - 1) / WARPS_PER_BLOCK;
    iln_kernel<<<blocks, NTHREADS>>>(x, weight, bias, out, n_rows);
}

// round 16
// speedup vs baseline: 1.6176x; 1.0014x over previous
#include <cuda_runtime.h>
#include <math.h>

#define DIM 1024
#define WARPS_PER_BLOCK 8
#define NTHREADS 256

// Integer LayerNorm, warp per row, SINGLE pass over x:
// load row once -> convert to int regs (kept) -> REDUX stats -> 5-instr/elem
// epilogue straight from registers -> streaming store.
__global__ __launch_bounds__(NTHREADS, 4)
void iln_kernel(const float* __restrict__ x,
                const float* __restrict__ weight,
                const float* __restrict__ bias,
                float* __restrict__ out,
                int n_rows)
{
    __shared__ int   s_w[DIM];
    __shared__ float s_fb[DIM];          // bias_int / 256 as float (exact)
    __shared__ int   s_lut[32];

    const int tid = threadIdx.x;

    // 32-entry isqrt LUT, exact: round((1<<15)/sqrt(2^parity*(1+m/16)))
    if (tid < 32) {
        const int parity = tid >> 4;
        const int mant = tid & 15;
        const double val = (double)(1 << parity) * (1.0 + (double)mant * 0.0625);
        s_lut[tid] = (int)llrint(32768.0 / sqrt(val));
    }
    // Quantize weight/bias (round-half-even matches jnp.round)
    for (int i = tid; i < DIM; i += NTHREADS) {
        s_w[i]  = __float2int_rn(weight[i] * 256.0f);
        s_fb[i] = (float)__float2int_rn(bias[i] * 256.0f) * 0.00390625f;
    }
    __syncthreads();

    const int warp = tid >> 5;
    const int lane = tid & 31;
    const int row = blockIdx.x * WARPS_PER_BLOCK + warp;
    if (row >= n_rows) return;

    const float4* __restrict__ xr = (const float4*)(x + (size_t)row * DIM);

    // ---- single load pass: front-batched 8x LDG.128, convert once, KEEP xi ----
    float4 v[8];
    #pragma unroll
    for (int j = 0; j < 8; j++) v[j] = xr[j * 32 + lane];

    int xi[32];
    int sum = 0, sumsq = 0;              // row sumsq ~1e8 << 2^31, exact
    #pragma unroll
    for (int j = 0; j < 8; j++) {
        const int a0 = __float2int_rn(v[j].x);
        const int a1 = __float2int_rn(v[j].y);
        const int a2 = __float2int_rn(v[j].z);
        const int a3 = __float2int_rn(v[j].w);
        xi[j * 4 + 0] = a0; xi[j * 4 + 1] = a1;
        xi[j * 4 + 2] = a2; xi[j * 4 + 3] = a3;
        sum   += a0 + a1 + a2 + a3;
        sumsq += a0 * a0 + a1 * a1 + a2 * a2 + a3 * a3;
    }
    sum   = __reduce_add_sync(0xffffffffu, sum);
    sumsq = __reduce_add_sync(0xffffffffu, sumsq);

    const int mean = (sum * 64) >> 16;                 // fixed-point mean
    const long long ssy = (long long)sumsq
                        - 2LL * (long long)mean * (long long)sum
                        + (long long)DIM * (long long)mean * (long long)mean;
    long long var = (ssy * 64) >> 16;
    if (var < 1) var = 1;

    const int k = 63 - __clzll((unsigned long long)var);   // floor(log2), exact
    const int sa = k - 4;
    const int mant = (sa >= 0) ? (int)((var >> sa) & 15)
                               : (int)((var << (-sa)) & 15);
    const int inv = s_lut[((k & 1) << 4) | mant];
    const int ts = (k >> 1) + 15;        // p + SHIFT(0) + Q_LUT(15), ts in [15, ~24]
    const int minv = mean * inv;         // hoisted: s = a*inv - minv

    // ---- epilogue straight from registers ----
    float4* __restrict__ orow = (float4*)(out + (size_t)row * DIM);
    #pragma unroll
    for (int j = 0; j < 8; j++) {
        const int c4 = j * 32 + lane;
        const int4   w4 = ((const int4*)s_w)[c4];
        const float4 f4 = ((const float4*)s_fb)[c4];
        float4 o;
        // per element: IMAD, IMAD.WIDE, SHF, I2F, FFMA (exact; shifted result fits
        // int32 since |s|<2^25, |w|<2^10 => |prod|<2^34, >>ts>=15 => |res|<2^19)
        {
            const int s = xi[j*4+0] * inv - minv;
            const int lo = s * w4.x, hi = __mulhi(s, w4.x);
            o.x = fmaf((float)(int)__funnelshift_r((unsigned)lo, (unsigned)hi, ts),
                       0.00390625f, f4.x);
        }
        {
            const int s = xi[j*4+1] * inv - minv;
            const int lo = s * w4.y, hi = __mulhi(s, w4.y);
            o.y = fmaf((float)(int)__funnelshift_r((unsigned)lo, (unsigned)hi, ts),
                       0.00390625f, f4.y);
        }
        {
            const int s = xi[j*4+2] * inv - minv;
            const int lo = s * w4.z, hi = __mulhi(s, w4.z);
            o.z = fmaf((float)(int)__funnelshift_r((unsigned)lo, (unsigned)hi, ts),
                       0.00390625f, f4.z);
        }
        {
            const int s = xi[j*4+3] * inv - minv;
            const int lo = s * w4.w, hi = __mulhi(s, w4.w);
            o.w = fmaf((float)(int)__funnelshift_r((unsigned)lo, (unsigned)hi, ts),
                       0.00390625f, f4.w);
        }
        __stcs(&orow[c4], o);
    }
}

extern "C" void kernel_launch(void* const* d_in, const int* in_sizes, int n_in,
                              void* d_out, int out_size) {
    const float* x      = (const float*)d_in[0];
    const float* weight = (const float*)d_in[1];
    const float* bias   = (const float*)d_in[2];
    // d_in[3] (isqrt_lut) intentionally unused: LUT recomputed exactly in-kernel.
    float* out = (float*)d_out;

    const int n_rows = in_sizes[0] / DIM;
    const int blocks = (n_rows + WARPS_PER_BLOCK - 1) / WARPS_PER_BLOCK;
    iln_kernel<<<blocks, NTHREADS>>>(x, weight, bias, out, n_rows);
}

// round 17
// speedup vs baseline: 1.6333x; 1.0097x over previous
#include <cuda_runtime.h>
#include <math.h>

#define DIM 1024
#define WARPS_PER_BLOCK 8
#define NTHREADS 256
#define MAGICF 12582912.0f      // 1.5 * 2^23: round-half-even for |x| < 2^22
#define MAGICI 0x4B400000       // bit pattern of 12582912.0f

// Integer LayerNorm, warp per row, single pass, ZERO conversion-pipe ops:
// round-to-int via float magic-add (FADD+IADD), int->float via magic bitcast
// folded into the output FFMA. All math on full-rate fma/alu pipes. Bit-exact.
__global__ __launch_bounds__(NTHREADS, 4)
void iln_kernel(const float* __restrict__ x,
                const float* __restrict__ weight,
                const float* __restrict__ bias,
                float* __restrict__ out,
                int n_rows)
{
    __shared__ int   s_w[DIM];
    __shared__ float s_fb[DIM];   // b_int/256 - 49152.0f (exact; pairs with magic FFMA)
    __shared__ int   s_lut[32];

    const int tid = threadIdx.x;

    // 32-entry isqrt LUT, exact: round((1<<15)/sqrt(2^parity*(1+m/16)))
    if (tid < 32) {
        const int parity = tid >> 4;
        const int mant = tid & 15;
        const double val = (double)(1 << parity) * (1.0 + (double)mant * 0.0625);
        s_lut[tid] = (int)llrint(32768.0 / sqrt(val));
    }
    // Quantize weight/bias (round-half-even matches jnp.round).
    // s_fb = b_int/256 - 49152 : exact float (numerator |b_int - 12582912| < 2^24).
    for (int i = tid; i < DIM; i += NTHREADS) {
        s_w[i]  = __float2int_rn(weight[i] * 256.0f);
        s_fb[i] = (float)__float2int_rn(bias[i] * 256.0f) * 0.00390625f - 49152.0f;
    }
    __syncthreads();

    const int warp = tid >> 5;
    const int lane = tid & 31;
    const int row = blockIdx.x * WARPS_PER_BLOCK + warp;
    if (row >= n_rows) return;

    const float4* __restrict__ xr = (const float4*)(x + (size_t)row * DIM);

    // ---- single load pass: front-batched 8x LDG.128 ----
    float4 v[8];
    #pragma unroll
    for (int j = 0; j < 8; j++) v[j] = xr[j * 32 + lane];

    // Convert via magic add (FADD+IADD, no F2I), keep ints in regs.
    int xi[32];
    int sum = 0, sumsq = 0;              // row sumsq ~1e8 << 2^31, exact
    #pragma unroll
    for (int j = 0; j < 8; j++) {
        const int a0 = __float_as_int(v[j].x + MAGICF) - MAGICI;
        const int a1 = __float_as_int(v[j].y + MAGICF) - MAGICI;
        const int a2 = __float_as_int(v[j].z + MAGICF) - MAGICI;
        const int a3 = __float_as_int(v[j].w + MAGICF) - MAGICI;
        xi[j * 4 + 0] = a0; xi[j * 4 + 1] = a1;
        xi[j * 4 + 2] = a2; xi[j * 4 + 3] = a3;
        sum   += a0 + a1 + a2 + a3;
        sumsq += a0 * a0 + a1 * a1 + a2 * a2 + a3 * a3;
    }
    sum   = __reduce_add_sync(0xffffffffu, sum);
    sumsq = __reduce_add_sync(0xffffffffu, sumsq);

    const int mean = (sum * 64) >> 16;                 // fixed-point mean
    const long long ssy = (long long)sumsq
                        - 2LL * (long long)mean * (long long)sum
                        + (long long)DIM * (long long)mean * (long long)mean;
    long long var = (ssy * 64) >> 16;
    if (var < 1) var = 1;

    const int k = 63 - __clzll((unsigned long long)var);   // floor(log2), exact
    const int sa = k - 4;
    const int mant = (sa >= 0) ? (int)((var >> sa) & 15)
                               : (int)((var << (-sa)) & 15);
    const int inv = s_lut[((k & 1) << 4) | mant];
    const int ts = (k >> 1) + 15;        // p + SHIFT(0) + Q_LUT(15), ts in [15, ~24]
    const int minv = mean * inv;         // hoisted: s = a*inv - minv

    // ---- epilogue from registers; int->float via magic bitcast + FFMA ----
    float4* __restrict__ orow = (float4*)(out + (size_t)row * DIM);
    #pragma unroll
    for (int j = 0; j < 8; j++) {
        const int c4 = j * 32 + lane;
        const int4   w4 = ((const int4*)s_w)[c4];
        const float4 f4 = ((const float4*)s_fb)[c4];
        float4 o;
        // per element: IMAD, IMAD.WIDE(2), SHF, IADD, FFMA — all full-rate pipes.
        // Exact: |s|<2^25, |w|<2^10 => |prod|<2^34; >>ts (>=15) => |t|<2^19;
        // (12582912+t)*2^-8 + (b/256-49152) == (t+b)/256, single FFMA rounding of
        // an exactly-representable value.
        {
            const int s = xi[j*4+0] * inv - minv;
            const int t = (int)__funnelshift_r((unsigned)(s * w4.x),
                                               (unsigned)__mulhi(s, w4.x), ts);
            o.x = fmaf(__int_as_float(t + MAGICI), 0.00390625f, f4.x);
        }
        {
            const int s = xi[j*4+1] * inv - minv;
            const int t = (int)__funnelshift_r((unsigned)(s * w4.y),
                                               (unsigned)__mulhi(s, w4.y), ts);
            o.y = fmaf(__int_as_float(t + MAGICI), 0.00390625f, f4.y);
        }
        {
            const int s = xi[j*4+2] * inv - minv;
            const int t = (int)__funnelshift_r((unsigned)(s * w4.z),
                                               (unsigned)__mulhi(s, w4.z), ts);
            o.z = fmaf(__int_as_float(t + MAGICI), 0.00390625f, f4.z);
        }
        {
            const int s = xi[j*4+3] * inv - minv;
            const int t = (int)__funnelshift_r((unsigned)(s * w4.w),
                                               (unsigned)__mulhi(s, w4.w), ts);
            o.w = fmaf(__int_as_float(t + MAGICI), 0.00390625f, f4.w);
        }
        __stcs(&orow[c4], o);
    }
}

extern "C" void kernel_launch(void* const* d_in, const int* in_sizes, int n_in,
                              void* d_out, int out_size) {
    const float* x      = (const float*)d_in[0];
    const float* weight = (const float*)d_in[1];
    const float* bias   = (const float*)d_in[2];
    // d_in[3] (isqrt_lut) intentionally unused: LUT recomputed exactly in-kernel.
    float* out = (float*)d_out;

    const int n_rows = in_sizes[0] / DIM;
    const int blocks = (n_rows + WARPS_PER_BLOCK - 1) / WARPS_PER_BLOCK;
    iln_kernel<<<blocks, NTHREADS>>>(x, weight, bias, out, n_rows);
}